// round 14
// baseline (speedup 1.0000x reference)
#include <cuda_runtime.h>
#include <cuda_fp16.h>

// LightGCN 3-layer propagation, N=200000, E=3.2M, D=64+64 fused to 128.
// R14 = R4 champion (768us, reproduced exactly) + padded/aligned CSR:
// each node's edge segment is padded to a multiple of 4 entries with
// (src=0, w=0) sentinels -> gather loop has NO tail, and each 4-edge group
// is 32B-aligned so CSR loads are two LDG.128s. Padding gathers hit row 0
// (L1-hot) and add exactly 0. Inner math otherwise byte-identical to R4.
// NOTE: __device__ globals referenced ONLY from device code.

#define USER_NUM 100000
#define N_NODES  200000
#define NE       3200000
#define NE_PAD   (NE + 3 * N_NODES)   // worst-case +3 per node

__device__ int   g_cnt[N_NODES];
__device__ int   g_rowptr[N_NODES + 1];
__device__ float g_dis[N_NODES];
__device__ __align__(16) int2 g_csr[NE_PAD];       // (src, norm-bits)
__device__ uint2 g_e0h[(size_t)N_NODES * 32];      // fp16 rows, 256B each
__device__ uint2 g_e1h[(size_t)N_NODES * 32];
__device__ uint2 g_e2h[(size_t)N_NODES * 32];

// ---- fp16 <-> fp32 row-chunk helpers (4 floats <-> uint2) ------------------
__device__ __forceinline__ uint2 f4_to_h(float4 v) {
    __half2 lo = __floats2half2_rn(v.x, v.y);
    __half2 hi = __floats2half2_rn(v.z, v.w);
    uint2 u;
    u.x = *reinterpret_cast<unsigned*>(&lo);
    u.y = *reinterpret_cast<unsigned*>(&hi);
    return u;
}
__device__ __forceinline__ float4 h_to_f4(uint2 u) {
    __half2 lo = *reinterpret_cast<__half2*>(&u.x);
    __half2 hi = *reinterpret_cast<__half2*>(&u.y);
    float2 a = __half22float2(lo);
    float2 b = __half22float2(hi);
    return make_float4(a.x, a.y, b.x, b.y);
}

// ---------------------------------------------------------------------------
__global__ void k_zero() {
    int i = blockIdx.x * blockDim.x + threadIdx.x;
    int stride = gridDim.x * blockDim.x;
    for (; i < N_NODES; i += stride) g_cnt[i] = 0;
}

__global__ void k_count(const int* __restrict__ dst) {
    int i = blockIdx.x * blockDim.x + threadIdx.x;
    int stride = gridDim.x * blockDim.x;
    for (; i < NE; i += stride) {
        atomicAdd(&g_cnt[dst[i]], 1);
    }
}

// Single-block exclusive scan of PADDED counts -> g_rowptr; computes g_dis.
// Resets g_cnt to 0 (reused as scatter cursor). rowptr entries are all
// multiples of 4 => every node's 4-edge groups are 32B-aligned.
__global__ void k_scan() {
    __shared__ int sums[1024];
    const int t = threadIdx.x;
    const int CH = (N_NODES + 1023) / 1024;   // 196
    int beg = t * CH;
    int end = beg + CH; if (end > N_NODES) end = N_NODES;

    int s = 0;
    for (int i = beg; i < end; i++) {
        int c = g_cnt[i];
        s += (c + 3) & ~3;
        g_dis[i] = (c > 0) ? rsqrtf((float)c) : 0.0f;
    }
    sums[t] = s;
    __syncthreads();

    for (int off = 1; off < 1024; off <<= 1) {
        int v = 0;
        if (t >= off) v = sums[t - off];
        __syncthreads();
        sums[t] += v;
        __syncthreads();
    }

    int run = (t == 0) ? 0 : sums[t - 1];
    for (int i = beg; i < end; i++) {
        g_rowptr[i] = run;
        run += (g_cnt[i] + 3) & ~3;
        g_cnt[i] = 0;                 // becomes the scatter cursor
    }
    if (t == 1023) g_rowptr[N_NODES] = run;
}

__global__ void k_scatter(const int* __restrict__ src, const int* __restrict__ dst) {
    int i = blockIdx.x * blockDim.x + threadIdx.x;
    int stride = gridDim.x * blockDim.x;
    for (; i < NE; i += stride) {
        int s = src[i];
        int d = dst[i];
        int pos = g_rowptr[d] + atomicAdd(&g_cnt[d], 1);
        float w = g_dis[s] * g_dis[d];
        g_csr[pos] = make_int2(s, __float_as_int(w));
    }
}

// Fill each node's padding slots [rowptr[n]+deg, rowptr[n+1]) with
// (src=0, w=0): contributes exactly 0, and row 0 stays L1-hot.
__global__ void k_fillpad() {
    int n = blockIdx.x * blockDim.x + threadIdx.x;
    if (n >= N_NODES) return;
    int p   = g_rowptr[n] + g_cnt[n];     // g_cnt[n] == true degree now
    int end = g_rowptr[n + 1];
    for (; p < end; ++p) g_csr[p] = make_int2(0, 0);
}

// Per-lane float4 chunk of the fused 128-col row, from the original inputs.
__device__ __forceinline__ float4 load_input_chunk(
    const float4* __restrict__ ui, const float4* __restrict__ ii,
    const float4* __restrict__ ug, const float4* __restrict__ ig,
    int node, int lane)
{
    if (lane < 16) {
        return (node < USER_NUM) ? ui[node * 16 + lane]
                                 : ii[(node - USER_NUM) * 16 + lane];
    } else {
        int q = lane - 16;
        return (node < USER_NUM) ? ug[node * 16 + q]
                                 : ig[(node - USER_NUM) * 16 + q];
    }
}

// Pack inputs into fused fp16 rows (e0h).
__global__ void k_pack(const float4* __restrict__ ui, const float4* __restrict__ ii,
                       const float4* __restrict__ ug, const float4* __restrict__ ig) {
    int idx = blockIdx.x * blockDim.x + threadIdx.x;
    int stride = gridDim.x * blockDim.x;
    const int total = N_NODES * 32;
    for (; idx < total; idx += stride) {
        int node = idx >> 5;
        int lane = idx & 31;
        g_e0h[idx] = f4_to_h(load_input_chunk(ui, ii, ug, ig, node, lane));
    }
}

// Gather core: tail-free, 4 edges/iter, CSR via two aligned LDG.128s.
// fp32 accumulation over fp16 rows; math identical to R4.
__device__ __forceinline__ float4 gather_node(const uint2* __restrict__ xin,
                                              int node, int lane) {
    int beg = __ldg(&g_rowptr[node]);       // multiple of 4
    int end = __ldg(&g_rowptr[node + 1]);   // multiple of 4
    float4 a = make_float4(0.f, 0.f, 0.f, 0.f);
    for (int i = beg; i < end; i += 4) {
        int4 p = __ldg(reinterpret_cast<const int4*>(g_csr + i));      // s0,w0,s1,w1
        int4 q = __ldg(reinterpret_cast<const int4*>(g_csr + i + 2));  // s2,w2,s3,w3
        uint2 u0 = __ldg(&xin[p.x * 32 + lane]);
        uint2 u1 = __ldg(&xin[p.z * 32 + lane]);
        uint2 u2 = __ldg(&xin[q.x * 32 + lane]);
        uint2 u3 = __ldg(&xin[q.z * 32 + lane]);
        float w0 = __int_as_float(p.y), w1 = __int_as_float(p.w);
        float w2 = __int_as_float(q.y), w3 = __int_as_float(q.w);
        float4 v0 = h_to_f4(u0), v1 = h_to_f4(u1);
        float4 v2 = h_to_f4(u2), v3 = h_to_f4(u3);
        a.x += w0 * v0.x + w1 * v1.x + w2 * v2.x + w3 * v3.x;
        a.y += w0 * v0.y + w1 * v1.y + w2 * v2.y + w3 * v3.y;
        a.z += w0 * v0.z + w1 * v1.z + w2 * v2.z + w3 * v3.z;
        a.w += w0 * v0.w + w1 * v1.w + w2 * v2.w + w3 * v3.w;
    }
    return a;
}

// Layers 1 & 2: gather -> write fp16. Buffers selected in DEVICE code.
// layer==1: e0h -> e1h ; layer==2: e1h -> e2h
__global__ void __launch_bounds__(256) k_prop12(int layer) {
    int gtid = blockIdx.x * blockDim.x + threadIdx.x;
    int node = gtid >> 5;
    if (node >= N_NODES) return;
    int lane = threadIdx.x & 31;

    const uint2* xin  = (layer == 1) ? g_e0h : g_e1h;
    uint2*       xout = (layer == 1) ? g_e1h : g_e2h;

    float4 a = gather_node(xin, node, lane);
    xout[node * 32 + lane] = f4_to_h(a);
}

// Layer 3 fused with final reduction:
// out = (e0_fp32 + e1 + e2 + conv(e2)) / 16, split into [int | geo] sections.
__global__ void __launch_bounds__(256) k_prop3(
    const float4* __restrict__ ui, const float4* __restrict__ ii,
    const float4* __restrict__ ug, const float4* __restrict__ ig,
    float4* __restrict__ out)
{
    int gtid = blockIdx.x * blockDim.x + threadIdx.x;
    int node = gtid >> 5;
    if (node >= N_NODES) return;
    int lane = threadIdx.x & 31;

    float4 a = gather_node(g_e2h, node, lane);           // layer-3 output

    float4 base = load_input_chunk(ui, ii, ug, ig, node, lane);  // e0 (fp32)
    float4 v1 = h_to_f4(__ldg(&g_e1h[node * 32 + lane]));
    float4 v2 = h_to_f4(__ldg(&g_e2h[node * 32 + lane]));

    const float s = 1.0f / 16.0f;
    float4 r;
    r.x = (base.x + v1.x + v2.x + a.x) * s;
    r.y = (base.y + v1.y + v2.y + a.y) * s;
    r.z = (base.z + v1.z + v2.z + a.z) * s;
    r.w = (base.w + v1.w + v2.w + a.w) * s;

    const int geo_base = N_NODES * 16;
    if (lane < 16) out[node * 16 + lane] = r;
    else           out[geo_base + node * 16 + (lane - 16)] = r;
}

// ---------------------------------------------------------------------------
extern "C" void kernel_launch(void* const* d_in, const int* in_sizes, int n_in,
                              void* d_out, int out_size) {
    const float4* user_int = (const float4*)d_in[0];
    const float4* item_int = (const float4*)d_in[1];
    const float4* user_geo = (const float4*)d_in[2];
    const float4* item_geo = (const float4*)d_in[3];
    const int*    edge     = (const int*)d_in[4];
    const int* src = edge;        // row 0 of [2, E]
    const int* dst = edge + NE;   // row 1

    float4* out = (float4*)d_out;

    const int TB = 256;
    const int prop_blocks = (N_NODES * 32 + TB - 1) / TB;   // 25000
    const int node_blocks = (N_NODES + TB - 1) / TB;        // 782

    k_zero<<<512, TB>>>();
    k_count<<<4096, TB>>>(dst);
    k_scan<<<1, 1024>>>();
    k_scatter<<<4096, TB>>>(src, dst);
    k_fillpad<<<node_blocks, TB>>>();
    k_pack<<<prop_blocks, TB>>>(user_int, item_int, user_geo, item_geo);

    k_prop12<<<prop_blocks, TB>>>(1);   // layer 1: e0h -> e1h
    k_prop12<<<prop_blocks, TB>>>(2);   // layer 2: e1h -> e2h
    k_prop3<<<prop_blocks, TB>>>(user_int, item_int, user_geo, item_geo, out);
}

// round 15
// speedup vs baseline: 1.1760x; 1.1760x over previous
#include <cuda_runtime.h>
#include <cuda_fp16.h>

// LightGCN 3-layer propagation, N=200000, E=3.2M, D=64+64 fused to 128.
// R15 = R4 champion with ONE change: gather unroll 4 -> 8 in the identical
// idiom (per-int2 __ldg CSR loads, same guard, same serial tail). All other
// kernels byte-identical to R4 (768us, reproduced deterministically).
// History: every structural change to this loop (pipeline/chunk/int4/split)
// regressed 25-45%; unroll depth is the one unexplored axis.
// NOTE: __device__ globals referenced ONLY from device code.

#define USER_NUM 100000
#define N_NODES  200000
#define NE       3200000

__device__ int   g_cnt[N_NODES];
__device__ int   g_cursor[N_NODES];
__device__ int   g_rowptr[N_NODES + 1];
__device__ float g_dis[N_NODES];
__device__ int2  g_csr[NE];                        // (src, norm-bits)
__device__ uint2 g_e0h[(size_t)N_NODES * 32];      // fp16 rows, 256B each
__device__ uint2 g_e1h[(size_t)N_NODES * 32];
__device__ uint2 g_e2h[(size_t)N_NODES * 32];

// ---- fp16 <-> fp32 row-chunk helpers (4 floats <-> uint2) ------------------
__device__ __forceinline__ uint2 f4_to_h(float4 v) {
    __half2 lo = __floats2half2_rn(v.x, v.y);
    __half2 hi = __floats2half2_rn(v.z, v.w);
    uint2 u;
    u.x = *reinterpret_cast<unsigned*>(&lo);
    u.y = *reinterpret_cast<unsigned*>(&hi);
    return u;
}
__device__ __forceinline__ float4 h_to_f4(uint2 u) {
    __half2 lo = *reinterpret_cast<__half2*>(&u.x);
    __half2 hi = *reinterpret_cast<__half2*>(&u.y);
    float2 a = __half22float2(lo);
    float2 b = __half22float2(hi);
    return make_float4(a.x, a.y, b.x, b.y);
}

// ---------------------------------------------------------------------------
__global__ void k_zero() {
    int i = blockIdx.x * blockDim.x + threadIdx.x;
    int stride = gridDim.x * blockDim.x;
    for (; i < N_NODES; i += stride) {
        g_cnt[i] = 0;
        g_cursor[i] = 0;
    }
}

__global__ void k_count(const int* __restrict__ dst) {
    int i = blockIdx.x * blockDim.x + threadIdx.x;
    int stride = gridDim.x * blockDim.x;
    for (; i < NE; i += stride) {
        atomicAdd(&g_cnt[dst[i]], 1);
    }
}

// Single-block exclusive scan over g_cnt -> g_rowptr; also computes g_dis.
__global__ void k_scan() {
    __shared__ int sums[1024];
    const int t = threadIdx.x;
    const int CH = (N_NODES + 1023) / 1024;   // 196
    int beg = t * CH;
    int end = beg + CH; if (end > N_NODES) end = N_NODES;

    int s = 0;
    for (int i = beg; i < end; i++) {
        int c = g_cnt[i];
        s += c;
        g_dis[i] = (c > 0) ? rsqrtf((float)c) : 0.0f;
    }
    sums[t] = s;
    __syncthreads();

    for (int off = 1; off < 1024; off <<= 1) {
        int v = 0;
        if (t >= off) v = sums[t - off];
        __syncthreads();
        sums[t] += v;
        __syncthreads();
    }

    int run = (t == 0) ? 0 : sums[t - 1];
    for (int i = beg; i < end; i++) {
        g_rowptr[i] = run;
        run += g_cnt[i];
    }
    if (t == 1023) g_rowptr[N_NODES] = run;
}

__global__ void k_scatter(const int* __restrict__ src, const int* __restrict__ dst) {
    int i = blockIdx.x * blockDim.x + threadIdx.x;
    int stride = gridDim.x * blockDim.x;
    for (; i < NE; i += stride) {
        int s = src[i];
        int d = dst[i];
        int pos = g_rowptr[d] + atomicAdd(&g_cursor[d], 1);
        float w = g_dis[s] * g_dis[d];
        g_csr[pos] = make_int2(s, __float_as_int(w));
    }
}

// Per-lane float4 chunk of the fused 128-col row, from the original inputs.
__device__ __forceinline__ float4 load_input_chunk(
    const float4* __restrict__ ui, const float4* __restrict__ ii,
    const float4* __restrict__ ug, const float4* __restrict__ ig,
    int node, int lane)
{
    if (lane < 16) {
        return (node < USER_NUM) ? ui[node * 16 + lane]
                                 : ii[(node - USER_NUM) * 16 + lane];
    } else {
        int q = lane - 16;
        return (node < USER_NUM) ? ug[node * 16 + q]
                                 : ig[(node - USER_NUM) * 16 + q];
    }
}

// Pack inputs into fused fp16 rows (e0h).
__global__ void k_pack(const float4* __restrict__ ui, const float4* __restrict__ ii,
                       const float4* __restrict__ ug, const float4* __restrict__ ig) {
    int idx = blockIdx.x * blockDim.x + threadIdx.x;
    int stride = gridDim.x * blockDim.x;
    const int total = N_NODES * 32;
    for (; idx < total; idx += stride) {
        int node = idx >> 5;
        int lane = idx & 31;
        g_e0h[idx] = f4_to_h(load_input_chunk(ui, ii, ug, ig, node, lane));
    }
}

// Gather core: R4 idiom, widened to 8 edges per iteration; serial tail.
__device__ __forceinline__ float4 gather_node(const uint2* __restrict__ xin,
                                              int node, int lane) {
    int beg = __ldg(&g_rowptr[node]);
    int end = __ldg(&g_rowptr[node + 1]);
    float4 a = make_float4(0.f, 0.f, 0.f, 0.f);
    int i = beg;
    for (; i + 8 <= end; i += 8) {
        int2 e0 = __ldg(&g_csr[i + 0]);
        int2 e1 = __ldg(&g_csr[i + 1]);
        int2 e2 = __ldg(&g_csr[i + 2]);
        int2 e3 = __ldg(&g_csr[i + 3]);
        int2 e4 = __ldg(&g_csr[i + 4]);
        int2 e5 = __ldg(&g_csr[i + 5]);
        int2 e6 = __ldg(&g_csr[i + 6]);
        int2 e7 = __ldg(&g_csr[i + 7]);
        uint2 u0 = __ldg(&xin[e0.x * 32 + lane]);
        uint2 u1 = __ldg(&xin[e1.x * 32 + lane]);
        uint2 u2 = __ldg(&xin[e2.x * 32 + lane]);
        uint2 u3 = __ldg(&xin[e3.x * 32 + lane]);
        uint2 u4 = __ldg(&xin[e4.x * 32 + lane]);
        uint2 u5 = __ldg(&xin[e5.x * 32 + lane]);
        uint2 u6 = __ldg(&xin[e6.x * 32 + lane]);
        uint2 u7 = __ldg(&xin[e7.x * 32 + lane]);
        float w0 = __int_as_float(e0.y), w1 = __int_as_float(e1.y);
        float w2 = __int_as_float(e2.y), w3 = __int_as_float(e3.y);
        float w4 = __int_as_float(e4.y), w5 = __int_as_float(e5.y);
        float w6 = __int_as_float(e6.y), w7 = __int_as_float(e7.y);
        float4 v0 = h_to_f4(u0), v1 = h_to_f4(u1);
        float4 v2 = h_to_f4(u2), v3 = h_to_f4(u3);
        float4 v4 = h_to_f4(u4), v5 = h_to_f4(u5);
        float4 v6 = h_to_f4(u6), v7 = h_to_f4(u7);
        a.x += w0 * v0.x + w1 * v1.x + w2 * v2.x + w3 * v3.x
             + w4 * v4.x + w5 * v5.x + w6 * v6.x + w7 * v7.x;
        a.y += w0 * v0.y + w1 * v1.y + w2 * v2.y + w3 * v3.y
             + w4 * v4.y + w5 * v5.y + w6 * v6.y + w7 * v7.y;
        a.z += w0 * v0.z + w1 * v1.z + w2 * v2.z + w3 * v3.z
             + w4 * v4.z + w5 * v5.z + w6 * v6.z + w7 * v7.z;
        a.w += w0 * v0.w + w1 * v1.w + w2 * v2.w + w3 * v3.w
             + w4 * v4.w + w5 * v5.w + w6 * v6.w + w7 * v7.w;
    }
    for (; i < end; ++i) {
        int2 e = __ldg(&g_csr[i]);
        float w = __int_as_float(e.y);
        float4 v = h_to_f4(__ldg(&xin[e.x * 32 + lane]));
        a.x += w * v.x; a.y += w * v.y; a.z += w * v.z; a.w += w * v.w;
    }
    return a;
}

// Layers 1 & 2: gather -> write fp16. Buffers selected in DEVICE code.
// layer==1: e0h -> e1h ; layer==2: e1h -> e2h
__global__ void __launch_bounds__(256) k_prop12(int layer) {
    int gtid = blockIdx.x * blockDim.x + threadIdx.x;
    int node = gtid >> 5;
    if (node >= N_NODES) return;
    int lane = threadIdx.x & 31;

    const uint2* xin  = (layer == 1) ? g_e0h : g_e1h;
    uint2*       xout = (layer == 1) ? g_e1h : g_e2h;

    float4 a = gather_node(xin, node, lane);
    xout[node * 32 + lane] = f4_to_h(a);
}

// Layer 3 fused with final reduction:
// out = (e0_fp32 + e1 + e2 + conv(e2)) / 16, split into [int | geo] sections.
__global__ void __launch_bounds__(256) k_prop3(
    const float4* __restrict__ ui, const float4* __restrict__ ii,
    const float4* __restrict__ ug, const float4* __restrict__ ig,
    float4* __restrict__ out)
{
    int gtid = blockIdx.x * blockDim.x + threadIdx.x;
    int node = gtid >> 5;
    if (node >= N_NODES) return;
    int lane = threadIdx.x & 31;

    float4 a = gather_node(g_e2h, node, lane);           // layer-3 output

    float4 base = load_input_chunk(ui, ii, ug, ig, node, lane);  // e0 (fp32)
    float4 v1 = h_to_f4(__ldg(&g_e1h[node * 32 + lane]));
    float4 v2 = h_to_f4(__ldg(&g_e2h[node * 32 + lane]));

    const float s = 1.0f / 16.0f;
    float4 r;
    r.x = (base.x + v1.x + v2.x + a.x) * s;
    r.y = (base.y + v1.y + v2.y + a.y) * s;
    r.z = (base.z + v1.z + v2.z + a.z) * s;
    r.w = (base.w + v1.w + v2.w + a.w) * s;

    const int geo_base = N_NODES * 16;
    if (lane < 16) out[node * 16 + lane] = r;
    else           out[geo_base + node * 16 + (lane - 16)] = r;
}

// ---------------------------------------------------------------------------
extern "C" void kernel_launch(void* const* d_in, const int* in_sizes, int n_in,
                              void* d_out, int out_size) {
    const float4* user_int = (const float4*)d_in[0];
    const float4* item_int = (const float4*)d_in[1];
    const float4* user_geo = (const float4*)d_in[2];
    const float4* item_geo = (const float4*)d_in[3];
    const int*    edge     = (const int*)d_in[4];
    const int* src = edge;        // row 0 of [2, E]
    const int* dst = edge + NE;   // row 1

    float4* out = (float4*)d_out;

    const int TB = 256;
    const int prop_blocks = (N_NODES * 32 + TB - 1) / TB;   // 25000

    k_zero<<<512, TB>>>();
    k_count<<<4096, TB>>>(dst);
    k_scan<<<1, 1024>>>();
    k_scatter<<<4096, TB>>>(src, dst);
    k_pack<<<prop_blocks, TB>>>(user_int, item_int, user_geo, item_geo);

    k_prop12<<<prop_blocks, TB>>>(1);   // layer 1: e0h -> e1h
    k_prop12<<<prop_blocks, TB>>>(2);   // layer 2: e1h -> e2h
    k_prop3<<<prop_blocks, TB>>>(user_int, item_int, user_geo, item_geo, out);
}

// round 16
// speedup vs baseline: 1.2514x; 1.0642x over previous
#include <cuda_runtime.h>
#include <cuda_fp16.h>

// LightGCN 3-layer propagation, N=200000, E=3.2M, D=64+64 fused to 128.
// R16 = R4 champion (768us, bit-reproducible) with ONE scheduling change:
// k_scatter and k_pack are independent (scatter writes g_csr from rowptr/dis;
// pack writes g_e0h from raw inputs only) — fuse them into a single kernel
// partitioned by blockIdx so the SM scheduler overlaps scatter's L2-atomic
// latency with pack's DRAM streaming. Both code paths are VERBATIM R4 loops.
// Gather loop, all other kernels: byte-identical to R4.
// NOTE: __device__ globals referenced ONLY from device code.

#define USER_NUM 100000
#define N_NODES  200000
#define NE       3200000
#define SC_BLOCKS 4096
#define PK_BLOCKS 4096

__device__ int   g_cnt[N_NODES];
__device__ int   g_cursor[N_NODES];
__device__ int   g_rowptr[N_NODES + 1];
__device__ float g_dis[N_NODES];
__device__ int2  g_csr[NE];                        // (src, norm-bits)
__device__ uint2 g_e0h[(size_t)N_NODES * 32];      // fp16 rows, 256B each
__device__ uint2 g_e1h[(size_t)N_NODES * 32];
__device__ uint2 g_e2h[(size_t)N_NODES * 32];

// ---- fp16 <-> fp32 row-chunk helpers (4 floats <-> uint2) ------------------
__device__ __forceinline__ uint2 f4_to_h(float4 v) {
    __half2 lo = __floats2half2_rn(v.x, v.y);
    __half2 hi = __floats2half2_rn(v.z, v.w);
    uint2 u;
    u.x = *reinterpret_cast<unsigned*>(&lo);
    u.y = *reinterpret_cast<unsigned*>(&hi);
    return u;
}
__device__ __forceinline__ float4 h_to_f4(uint2 u) {
    __half2 lo = *reinterpret_cast<__half2*>(&u.x);
    __half2 hi = *reinterpret_cast<__half2*>(&u.y);
    float2 a = __half22float2(lo);
    float2 b = __half22float2(hi);
    return make_float4(a.x, a.y, b.x, b.y);
}

// ---------------------------------------------------------------------------
__global__ void k_zero() {
    int i = blockIdx.x * blockDim.x + threadIdx.x;
    int stride = gridDim.x * blockDim.x;
    for (; i < N_NODES; i += stride) {
        g_cnt[i] = 0;
        g_cursor[i] = 0;
    }
}

__global__ void k_count(const int* __restrict__ dst) {
    int i = blockIdx.x * blockDim.x + threadIdx.x;
    int stride = gridDim.x * blockDim.x;
    for (; i < NE; i += stride) {
        atomicAdd(&g_cnt[dst[i]], 1);
    }
}

// Single-block exclusive scan over g_cnt -> g_rowptr; also computes g_dis.
__global__ void k_scan() {
    __shared__ int sums[1024];
    const int t = threadIdx.x;
    const int CH = (N_NODES + 1023) / 1024;   // 196
    int beg = t * CH;
    int end = beg + CH; if (end > N_NODES) end = N_NODES;

    int s = 0;
    for (int i = beg; i < end; i++) {
        int c = g_cnt[i];
        s += c;
        g_dis[i] = (c > 0) ? rsqrtf((float)c) : 0.0f;
    }
    sums[t] = s;
    __syncthreads();

    for (int off = 1; off < 1024; off <<= 1) {
        int v = 0;
        if (t >= off) v = sums[t - off];
        __syncthreads();
        sums[t] += v;
        __syncthreads();
    }

    int run = (t == 0) ? 0 : sums[t - 1];
    for (int i = beg; i < end; i++) {
        g_rowptr[i] = run;
        run += g_cnt[i];
    }
    if (t == 1023) g_rowptr[N_NODES] = run;
}

// Per-lane float4 chunk of the fused 128-col row, from the original inputs.
__device__ __forceinline__ float4 load_input_chunk(
    const float4* __restrict__ ui, const float4* __restrict__ ii,
    const float4* __restrict__ ug, const float4* __restrict__ ig,
    int node, int lane)
{
    if (lane < 16) {
        return (node < USER_NUM) ? ui[node * 16 + lane]
                                 : ii[(node - USER_NUM) * 16 + lane];
    } else {
        int q = lane - 16;
        return (node < USER_NUM) ? ug[node * 16 + q]
                                 : ig[(node - USER_NUM) * 16 + q];
    }
}

// Fused scatter + pack: blocks [0, SC_BLOCKS) run the R4 scatter loop;
// blocks [SC_BLOCKS, SC_BLOCKS+PK_BLOCKS) run the R4 pack loop. The two
// touch disjoint data and stress different resources (L2 atomics vs DRAM
// streaming), so co-residency overlaps them.
__global__ void k_scatter_pack(
    const int* __restrict__ src, const int* __restrict__ dst,
    const float4* __restrict__ ui, const float4* __restrict__ ii,
    const float4* __restrict__ ug, const float4* __restrict__ ig)
{
    if (blockIdx.x < SC_BLOCKS) {
        int i = blockIdx.x * blockDim.x + threadIdx.x;
        int stride = SC_BLOCKS * blockDim.x;
        for (; i < NE; i += stride) {
            int s = src[i];
            int d = dst[i];
            int pos = g_rowptr[d] + atomicAdd(&g_cursor[d], 1);
            float w = g_dis[s] * g_dis[d];
            g_csr[pos] = make_int2(s, __float_as_int(w));
        }
    } else {
        int idx = (blockIdx.x - SC_BLOCKS) * blockDim.x + threadIdx.x;
        int stride = PK_BLOCKS * blockDim.x;
        const int total = N_NODES * 32;
        for (; idx < total; idx += stride) {
            int node = idx >> 5;
            int lane = idx & 31;
            g_e0h[idx] = f4_to_h(load_input_chunk(ui, ii, ug, ig, node, lane));
        }
    }
}

// Shared gather core: fp32 accumulation over fp16 rows (R4 verbatim).
__device__ __forceinline__ float4 gather_node(const uint2* __restrict__ xin,
                                              int node, int lane) {
    int beg = __ldg(&g_rowptr[node]);
    int end = __ldg(&g_rowptr[node + 1]);
    float4 a = make_float4(0.f, 0.f, 0.f, 0.f);
    int i = beg;
    for (; i + 4 <= end; i += 4) {
        int2 e0 = __ldg(&g_csr[i + 0]);
        int2 e1 = __ldg(&g_csr[i + 1]);
        int2 e2 = __ldg(&g_csr[i + 2]);
        int2 e3 = __ldg(&g_csr[i + 3]);
        uint2 u0 = __ldg(&xin[e0.x * 32 + lane]);
        uint2 u1 = __ldg(&xin[e1.x * 32 + lane]);
        uint2 u2 = __ldg(&xin[e2.x * 32 + lane]);
        uint2 u3 = __ldg(&xin[e3.x * 32 + lane]);
        float w0 = __int_as_float(e0.y), w1 = __int_as_float(e1.y);
        float w2 = __int_as_float(e2.y), w3 = __int_as_float(e3.y);
        float4 v0 = h_to_f4(u0), v1 = h_to_f4(u1);
        float4 v2 = h_to_f4(u2), v3 = h_to_f4(u3);
        a.x += w0 * v0.x + w1 * v1.x + w2 * v2.x + w3 * v3.x;
        a.y += w0 * v0.y + w1 * v1.y + w2 * v2.y + w3 * v3.y;
        a.z += w0 * v0.z + w1 * v1.z + w2 * v2.z + w3 * v3.z;
        a.w += w0 * v0.w + w1 * v1.w + w2 * v2.w + w3 * v3.w;
    }
    for (; i < end; ++i) {
        int2 e = __ldg(&g_csr[i]);
        float w = __int_as_float(e.y);
        float4 v = h_to_f4(__ldg(&xin[e.x * 32 + lane]));
        a.x += w * v.x; a.y += w * v.y; a.z += w * v.z; a.w += w * v.w;
    }
    return a;
}

// Layers 1 & 2: gather -> write fp16. Buffers selected in DEVICE code.
// layer==1: e0h -> e1h ; layer==2: e1h -> e2h
__global__ void __launch_bounds__(256) k_prop12(int layer) {
    int gtid = blockIdx.x * blockDim.x + threadIdx.x;
    int node = gtid >> 5;
    if (node >= N_NODES) return;
    int lane = threadIdx.x & 31;

    const uint2* xin  = (layer == 1) ? g_e0h : g_e1h;
    uint2*       xout = (layer == 1) ? g_e1h : g_e2h;

    float4 a = gather_node(xin, node, lane);
    xout[node * 32 + lane] = f4_to_h(a);
}

// Layer 3 fused with final reduction:
// out = (e0_fp32 + e1 + e2 + conv(e2)) / 16, split into [int | geo] sections.
__global__ void __launch_bounds__(256) k_prop3(
    const float4* __restrict__ ui, const float4* __restrict__ ii,
    const float4* __restrict__ ug, const float4* __restrict__ ig,
    float4* __restrict__ out)
{
    int gtid = blockIdx.x * blockDim.x + threadIdx.x;
    int node = gtid >> 5;
    if (node >= N_NODES) return;
    int lane = threadIdx.x & 31;

    float4 a = gather_node(g_e2h, node, lane);           // layer-3 output

    float4 base = load_input_chunk(ui, ii, ug, ig, node, lane);  // e0 (fp32)
    float4 v1 = h_to_f4(__ldg(&g_e1h[node * 32 + lane]));
    float4 v2 = h_to_f4(__ldg(&g_e2h[node * 32 + lane]));

    const float s = 1.0f / 16.0f;
    float4 r;
    r.x = (base.x + v1.x + v2.x + a.x) * s;
    r.y = (base.y + v1.y + v2.y + a.y) * s;
    r.z = (base.z + v1.z + v2.z + a.z) * s;
    r.w = (base.w + v1.w + v2.w + a.w) * s;

    const int geo_base = N_NODES * 16;
    if (lane < 16) out[node * 16 + lane] = r;
    else           out[geo_base + node * 16 + (lane - 16)] = r;
}

// ---------------------------------------------------------------------------
extern "C" void kernel_launch(void* const* d_in, const int* in_sizes, int n_in,
                              void* d_out, int out_size) {
    const float4* user_int = (const float4*)d_in[0];
    const float4* item_int = (const float4*)d_in[1];
    const float4* user_geo = (const float4*)d_in[2];
    const float4* item_geo = (const float4*)d_in[3];
    const int*    edge     = (const int*)d_in[4];
    const int* src = edge;        // row 0 of [2, E]
    const int* dst = edge + NE;   // row 1

    float4* out = (float4*)d_out;

    const int TB = 256;
    const int prop_blocks = (N_NODES * 32 + TB - 1) / TB;   // 25000

    k_zero<<<512, TB>>>();
    k_count<<<4096, TB>>>(dst);
    k_scan<<<1, 1024>>>();
    k_scatter_pack<<<SC_BLOCKS + PK_BLOCKS, TB>>>(src, dst,
                                                  user_int, item_int,
                                                  user_geo, item_geo);

    k_prop12<<<prop_blocks, TB>>>(1);   // layer 1: e0h -> e1h
    k_prop12<<<prop_blocks, TB>>>(2);   // layer 2: e1h -> e2h
    k_prop3<<<prop_blocks, TB>>>(user_int, item_int, user_geo, item_geo, out);
}

// round 17
// speedup vs baseline: 1.2887x; 1.0297x over previous
#include <cuda_runtime.h>
#include <cuda_fp16.h>

// LightGCN 3-layer propagation, N=200000, E=3.2M, D=64+64 fused to 128.
// R17 = R16 with the fusion re-paired: k_scan is single-block (1 SM, ~20us,
// 147 SMs idle) and independent of k_pack -> fuse scan(block 0) + pack
// (blocks 1..N) so pack hides scan entirely; scatter returns to standalone
// R4 form (68us; R16 showed scatter+pack co-residency contend for L2/DRAM,
// costing 22us). Gather loop and all prop kernels byte-identical to R4.
// NOTE: __device__ globals referenced ONLY from device code.

#define USER_NUM 100000
#define N_NODES  200000
#define NE       3200000

__device__ int   g_cnt[N_NODES];
__device__ int   g_cursor[N_NODES];
__device__ int   g_rowptr[N_NODES + 1];
__device__ float g_dis[N_NODES];
__device__ int2  g_csr[NE];                        // (src, norm-bits)
__device__ uint2 g_e0h[(size_t)N_NODES * 32];      // fp16 rows, 256B each
__device__ uint2 g_e1h[(size_t)N_NODES * 32];
__device__ uint2 g_e2h[(size_t)N_NODES * 32];

// ---- fp16 <-> fp32 row-chunk helpers (4 floats <-> uint2) ------------------
__device__ __forceinline__ uint2 f4_to_h(float4 v) {
    __half2 lo = __floats2half2_rn(v.x, v.y);
    __half2 hi = __floats2half2_rn(v.z, v.w);
    uint2 u;
    u.x = *reinterpret_cast<unsigned*>(&lo);
    u.y = *reinterpret_cast<unsigned*>(&hi);
    return u;
}
__device__ __forceinline__ float4 h_to_f4(uint2 u) {
    __half2 lo = *reinterpret_cast<__half2*>(&u.x);
    __half2 hi = *reinterpret_cast<__half2*>(&u.y);
    float2 a = __half22float2(lo);
    float2 b = __half22float2(hi);
    return make_float4(a.x, a.y, b.x, b.y);
}

// ---------------------------------------------------------------------------
__global__ void k_zero() {
    int i = blockIdx.x * blockDim.x + threadIdx.x;
    int stride = gridDim.x * blockDim.x;
    for (; i < N_NODES; i += stride) {
        g_cnt[i] = 0;
        g_cursor[i] = 0;
    }
}

__global__ void k_count(const int* __restrict__ dst) {
    int i = blockIdx.x * blockDim.x + threadIdx.x;
    int stride = gridDim.x * blockDim.x;
    for (; i < NE; i += stride) {
        atomicAdd(&g_cnt[dst[i]], 1);
    }
}

// Per-lane float4 chunk of the fused 128-col row, from the original inputs.
__device__ __forceinline__ float4 load_input_chunk(
    const float4* __restrict__ ui, const float4* __restrict__ ii,
    const float4* __restrict__ ug, const float4* __restrict__ ig,
    int node, int lane)
{
    if (lane < 16) {
        return (node < USER_NUM) ? ui[node * 16 + lane]
                                 : ii[(node - USER_NUM) * 16 + lane];
    } else {
        int q = lane - 16;
        return (node < USER_NUM) ? ug[node * 16 + q]
                                 : ig[(node - USER_NUM) * 16 + q];
    }
}

// Fused scan + pack: block 0 runs the single-block exclusive scan (R4
// verbatim: g_cnt -> g_rowptr, computes g_dis); blocks 1..gridDim-1 run the
// R4 pack loop (raw inputs -> fused fp16 rows e0h). Independent data; scan
// occupies 1 SM while pack streams on the rest.
__global__ void k_scan_pack(const float4* __restrict__ ui,
                            const float4* __restrict__ ii,
                            const float4* __restrict__ ug,
                            const float4* __restrict__ ig) {
    if (blockIdx.x == 0) {
        __shared__ int sums[1024];
        const int t = threadIdx.x;
        const int CH = (N_NODES + 1023) / 1024;   // 196
        int beg = t * CH;
        int end = beg + CH; if (end > N_NODES) end = N_NODES;

        int s = 0;
        for (int i = beg; i < end; i++) {
            int c = g_cnt[i];
            s += c;
            g_dis[i] = (c > 0) ? rsqrtf((float)c) : 0.0f;
        }
        sums[t] = s;
        __syncthreads();

        for (int off = 1; off < 1024; off <<= 1) {
            int v = 0;
            if (t >= off) v = sums[t - off];
            __syncthreads();
            sums[t] += v;
            __syncthreads();
        }

        int run = (t == 0) ? 0 : sums[t - 1];
        for (int i = beg; i < end; i++) {
            g_rowptr[i] = run;
            run += g_cnt[i];
        }
        if (t == 1023) g_rowptr[N_NODES] = run;
    } else {
        int idx = (blockIdx.x - 1) * blockDim.x + threadIdx.x;
        int stride = (gridDim.x - 1) * blockDim.x;
        const int total = N_NODES * 32;
        for (; idx < total; idx += stride) {
            int node = idx >> 5;
            int lane = idx & 31;
            g_e0h[idx] = f4_to_h(load_input_chunk(ui, ii, ug, ig, node, lane));
        }
    }
}

// CSR scatter (R4 verbatim, standalone).
__global__ void k_scatter(const int* __restrict__ src, const int* __restrict__ dst) {
    int i = blockIdx.x * blockDim.x + threadIdx.x;
    int stride = gridDim.x * blockDim.x;
    for (; i < NE; i += stride) {
        int s = src[i];
        int d = dst[i];
        int pos = g_rowptr[d] + atomicAdd(&g_cursor[d], 1);
        float w = g_dis[s] * g_dis[d];
        g_csr[pos] = make_int2(s, __float_as_int(w));
    }
}

// Shared gather core: fp32 accumulation over fp16 rows (R4 verbatim).
__device__ __forceinline__ float4 gather_node(const uint2* __restrict__ xin,
                                              int node, int lane) {
    int beg = __ldg(&g_rowptr[node]);
    int end = __ldg(&g_rowptr[node + 1]);
    float4 a = make_float4(0.f, 0.f, 0.f, 0.f);
    int i = beg;
    for (; i + 4 <= end; i += 4) {
        int2 e0 = __ldg(&g_csr[i + 0]);
        int2 e1 = __ldg(&g_csr[i + 1]);
        int2 e2 = __ldg(&g_csr[i + 2]);
        int2 e3 = __ldg(&g_csr[i + 3]);
        uint2 u0 = __ldg(&xin[e0.x * 32 + lane]);
        uint2 u1 = __ldg(&xin[e1.x * 32 + lane]);
        uint2 u2 = __ldg(&xin[e2.x * 32 + lane]);
        uint2 u3 = __ldg(&xin[e3.x * 32 + lane]);
        float w0 = __int_as_float(e0.y), w1 = __int_as_float(e1.y);
        float w2 = __int_as_float(e2.y), w3 = __int_as_float(e3.y);
        float4 v0 = h_to_f4(u0), v1 = h_to_f4(u1);
        float4 v2 = h_to_f4(u2), v3 = h_to_f4(u3);
        a.x += w0 * v0.x + w1 * v1.x + w2 * v2.x + w3 * v3.x;
        a.y += w0 * v0.y + w1 * v1.y + w2 * v2.y + w3 * v3.y;
        a.z += w0 * v0.z + w1 * v1.z + w2 * v2.z + w3 * v3.z;
        a.w += w0 * v0.w + w1 * v1.w + w2 * v2.w + w3 * v3.w;
    }
    for (; i < end; ++i) {
        int2 e = __ldg(&g_csr[i]);
        float w = __int_as_float(e.y);
        float4 v = h_to_f4(__ldg(&xin[e.x * 32 + lane]));
        a.x += w * v.x; a.y += w * v.y; a.z += w * v.z; a.w += w * v.w;
    }
    return a;
}

// Layers 1 & 2: gather -> write fp16. Buffers selected in DEVICE code.
// layer==1: e0h -> e1h ; layer==2: e1h -> e2h
__global__ void __launch_bounds__(256) k_prop12(int layer) {
    int gtid = blockIdx.x * blockDim.x + threadIdx.x;
    int node = gtid >> 5;
    if (node >= N_NODES) return;
    int lane = threadIdx.x & 31;

    const uint2* xin  = (layer == 1) ? g_e0h : g_e1h;
    uint2*       xout = (layer == 1) ? g_e1h : g_e2h;

    float4 a = gather_node(xin, node, lane);
    xout[node * 32 + lane] = f4_to_h(a);
}

// Layer 3 fused with final reduction:
// out = (e0_fp32 + e1 + e2 + conv(e2)) / 16, split into [int | geo] sections.
__global__ void __launch_bounds__(256) k_prop3(
    const float4* __restrict__ ui, const float4* __restrict__ ii,
    const float4* __restrict__ ug, const float4* __restrict__ ig,
    float4* __restrict__ out)
{
    int gtid = blockIdx.x * blockDim.x + threadIdx.x;
    int node = gtid >> 5;
    if (node >= N_NODES) return;
    int lane = threadIdx.x & 31;

    float4 a = gather_node(g_e2h, node, lane);           // layer-3 output

    float4 base = load_input_chunk(ui, ii, ug, ig, node, lane);  // e0 (fp32)
    float4 v1 = h_to_f4(__ldg(&g_e1h[node * 32 + lane]));
    float4 v2 = h_to_f4(__ldg(&g_e2h[node * 32 + lane]));

    const float s = 1.0f / 16.0f;
    float4 r;
    r.x = (base.x + v1.x + v2.x + a.x) * s;
    r.y = (base.y + v1.y + v2.y + a.y) * s;
    r.z = (base.z + v1.z + v2.z + a.z) * s;
    r.w = (base.w + v1.w + v2.w + a.w) * s;

    const int geo_base = N_NODES * 16;
    if (lane < 16) out[node * 16 + lane] = r;
    else           out[geo_base + node * 16 + (lane - 16)] = r;
}

// ---------------------------------------------------------------------------
extern "C" void kernel_launch(void* const* d_in, const int* in_sizes, int n_in,
                              void* d_out, int out_size) {
    const float4* user_int = (const float4*)d_in[0];
    const float4* item_int = (const float4*)d_in[1];
    const float4* user_geo = (const float4*)d_in[2];
    const float4* item_geo = (const float4*)d_in[3];
    const int*    edge     = (const int*)d_in[4];
    const int* src = edge;        // row 0 of [2, E]
    const int* dst = edge + NE;   // row 1

    float4* out = (float4*)d_out;

    const int TB = 256;
    const int prop_blocks = (N_NODES * 32 + TB - 1) / TB;   // 25000

    k_zero<<<512, TB>>>();
    k_count<<<4096, TB>>>(dst);
    // block 0: scan (needs 1024 threads); blocks 1..1024: pack
    k_scan_pack<<<1 + 1024, 1024>>>(user_int, item_int, user_geo, item_geo);
    k_scatter<<<4096, TB>>>(src, dst);

    k_prop12<<<prop_blocks, TB>>>(1);   // layer 1: e0h -> e1h
    k_prop12<<<prop_blocks, TB>>>(2);   // layer 2: e1h -> e2h
    k_prop3<<<prop_blocks, TB>>>(user_int, item_int, user_geo, item_geo, out);
}